// round 13
// baseline (speedup 1.0000x reference)
#include <cuda_runtime.h>
#include <cstdint>
#include <math.h>

#define H    8192      // DIM_HIDDEN
#define S    4096      // DIM_SOL (steps)
#define NB   2048      // blocks of 2 steps
#define CTX  4096      // DIM_CONTEXT
#define CSZ  8         // cluster size
#define NWW  8         // worker warps per CTA (wids 3..10)
#define WTH  256       // worker threads per CTA
#define TPB  352       // sender(0) + decider(1) + logp(2) + 8 workers
#define RDEP 4         // ring depth (blocks)

// ---------------- device scratch (static, no allocs) ----------------
__device__ float  g_Wt[(size_t)S * H];   // transposed W[:, CTX:]
__device__ float  g_Kt[(size_t)S * H];   // exp(-g_Wt)
__device__ float  g_a0[H];               // a0 = c + W[:, :CTX] @ context
__device__ float2 g_thr2[S];             // (t_hi, t_lo) two-float logit(u_i)

// ---------------- helpers ----------------
__device__ __forceinline__ float sigmoidf_fast(float x) {
    return __fdividef(1.0f, 1.0f + __expf(-x));
}
__device__ __forceinline__ float softplusf(float y) {
    float t = fabsf(y);
    float r = log1pf(__expf(-t));
    return (y > 0.f) ? (y + r) : r;
}
__device__ __forceinline__ unsigned cluster_rank() {
    unsigned r; asm("mov.u32 %0, %%cluster_ctarank;" : "=r"(r)); return r;
}
__device__ __forceinline__ uint32_t smem_u32(const void* p) {
    return (uint32_t)__cvta_generic_to_shared(p);
}
__device__ __forceinline__ void remote_store64(uint32_t laddr, unsigned rank, unsigned long long v) {
    uint32_t raddr;
    asm volatile("mapa.shared::cluster.u32 %0, %1, %2;" : "=r"(raddr) : "r"(laddr), "r"(rank));
    asm volatile("st.relaxed.cluster.shared::cluster.b64 [%0], %1;" :: "r"(raddr), "l"(v) : "memory");
}
__device__ __forceinline__ void cluster_barrier() {
    asm volatile("barrier.cluster.arrive.aligned;" ::: "memory");
    asm volatile("barrier.cluster.wait.aligned;"   ::: "memory");
}
__device__ __forceinline__ uint4 lds128v(const void* p) {
    uint4 r;
    asm volatile("ld.volatile.shared.v4.b32 {%0,%1,%2,%3}, [%4];"
                 : "=r"(r.x), "=r"(r.y), "=r"(r.z), "=r"(r.w) : "r"(smem_u32(p)));
    return r;
}
__device__ __forceinline__ void sts128(void* p, unsigned a, unsigned b, unsigned c, unsigned d) {
    asm volatile("st.shared.v4.b32 [%0], {%1,%2,%3,%4};"
                 :: "r"(smem_u32(p)), "r"(a), "r"(b), "r"(c), "r"(d) : "memory");
}
__device__ __forceinline__ void bfly4(float& a, float& b, float& c, float& d) {
    #pragma unroll
    for (int o = 16; o > 0; o >>= 1) {
        a += __shfl_xor_sync(0xffffffffu, a, o);
        b += __shfl_xor_sync(0xffffffffu, b, o);
        c += __shfl_xor_sync(0xffffffffu, c, o);
        d += __shfl_xor_sync(0xffffffffu, d, o);
    }
}
__device__ __forceinline__ bool thr_cmp(float x, float2 t) {
    return (x > t.x) || ((x == t.x) && (t.y < 0.f));
}

// ---------------- init kernels ----------------
__global__ void gemv_kernel(const float* __restrict__ W,
                            const float* __restrict__ ctxv,
                            const float* __restrict__ c) {
    __shared__ float sred[256];
    int r = blockIdx.x;
    const float* row = W + (size_t)r * (CTX + S);
    float acc = 0.f;
    for (int k = threadIdx.x; k < CTX; k += 256)
        acc += row[k] * ctxv[k];
    sred[threadIdx.x] = acc;
    __syncthreads();
    for (int off = 128; off > 0; off >>= 1) {
        if (threadIdx.x < off) sred[threadIdx.x] += sred[threadIdx.x + off];
        __syncthreads();
    }
    if (threadIdx.x == 0) g_a0[r] = c[r] + sred[0];
}

// transpose W[:, CTX:] and emit both Wt and Kt = exp(-Wt) in one pass
__global__ void transpose_kernel(const float* __restrict__ W) {
    __shared__ float tile[32][33];
    int i0 = blockIdx.x * 32;
    int j0 = blockIdx.y * 32;
    int tx = threadIdx.x;
    #pragma unroll
    for (int t = 0; t < 4; t++) {
        int ty = threadIdx.y + t * 8;
        tile[ty][tx] = W[(size_t)(j0 + ty) * (CTX + S) + CTX + i0 + tx];
    }
    __syncthreads();
    #pragma unroll
    for (int t = 0; t < 4; t++) {
        int ty = threadIdx.y + t * 8;
        float w = tile[tx][ty];
        size_t idx = (size_t)(i0 + ty) * H + j0 + tx;
        g_Wt[idx] = w;
        g_Kt[idx] = __expf(-w);
    }
}

__global__ void thr_kernel(const float* __restrict__ u) {
    int i = blockIdx.x * 256 + threadIdx.x;
    if (i < S) {
        double ud = (double)u[i];
        double t  = log(ud / (1.0 - ud));
        float hi  = (float)t;
        float lo  = (float)(t - (double)hi);
        g_thr2[i] = make_float2(hi, lo);
    }
}

// ---------------- main sequential kernel: 8-CTA cluster ----------------
// Block t = steps (2t, 2t+1).
// wpq[r][w][k]: 6 sandwich uint4 per worker warp:
//   k=0: {tag,q00,q01,tag}  k=1: {tag,q10,q11,tag}
//   k=2..5: {tag, o_{cb0}, o_{cb1}, tag} for cb = 00,01,10,11
// slots[r][idx*8+src]: tagged 64-bit; idx 0=E(even), 1=O(d=0), 2=O(d=1)
// dec[r]: (t<<2) | (s_{2t+1}<<1) | s_{2t}
__global__ void __cluster_dims__(CSZ, 1, 1) __launch_bounds__(TPB, 1)
nade_kernel(const float* __restrict__ V,
            const float* __restrict__ b,
            float* __restrict__ out,
            int out_size) {
    __shared__ __align__(16) uint4              wpq[RDEP][NWW][6];
    __shared__ __align__(16) unsigned long long slots[RDEP][24];
    __shared__ unsigned int       dec[RDEP];
    __shared__ unsigned long long xw[S];

    const unsigned rank = cluster_rank();
    const int tid  = threadIdx.x;
    const int wid  = tid >> 5;
    const int lane = tid & 31;
    const unsigned FULL = 0xffffffffu;

    for (int k = tid; k < RDEP * NWW * 6; k += TPB)
        ((uint4*)wpq)[k] = make_uint4(0xFFFFFFFFu, 0, 0, 0xFFFFFFFFu);
    for (int k = tid; k < RDEP * 24; k += TPB)
        ((unsigned long long*)slots)[k] = 0xFFFFFFFF00000000ULL;
    if (tid < RDEP) dec[tid] = 0xFFFFFFFFu;
    for (int k = tid; k < S; k += TPB)
        xw[k] = 0xFFFFFFFF00000000ULL;
    __syncthreads();
    cluster_barrier();   // all slots initialized before any remote store

    volatile unsigned int*       decv = dec;
    volatile unsigned long long* xwv  = xw;

    if (wid >= 3) {
        // ================= worker warps (wids 3..10) =================
        const int w    = wid - 3;
        const int wtid = tid - 96;                       // 0..255
        const int j0   = (int)rank * (WTH * 4) + wtid * 4;

        float a[4];
        float4 w8[8], k8[8], v8[8];                      // register rings (rows mod 8)

        auto publish = [&](int t, float q0, float q1, float q2, float q3,
                           float o0, float o1, float o2, float o3,
                           float o4, float o5, float o6, float o7) {
            bfly4(q0, q1, q2, q3);
            bfly4(o0, o1, o2, o3);
            bfly4(o4, o5, o6, o7);
            if (lane == 0) {
                unsigned tg = (unsigned)t;
                const int r = t & (RDEP - 1);
                sts128(&wpq[r][w][0], tg, __float_as_uint(q0), __float_as_uint(q1), tg);
                sts128(&wpq[r][w][1], tg, __float_as_uint(q2), __float_as_uint(q3), tg);
                sts128(&wpq[r][w][2], tg, __float_as_uint(o0), __float_as_uint(o1), tg);
                sts128(&wpq[r][w][3], tg, __float_as_uint(o2), __float_as_uint(o3), tg);
                sts128(&wpq[r][w][4], tg, __float_as_uint(o4), __float_as_uint(o5), tg);
                sts128(&wpq[r][w][5], tg, __float_as_uint(o6), __float_as_uint(o7), tg);
            }
        };

        // preload rings with rows 0..7
        #pragma unroll
        for (int rI = 0; rI < 8; rI++) {
            w8[rI] = *(const float4*)&g_Wt[(size_t)rI * H + j0];
            k8[rI] = *(const float4*)&g_Kt[(size_t)rI * H + j0];
            v8[rI] = *(const float4*)&V[(size_t)rI * H + j0];
        }
        {
            float4 av = *(const float4*)&g_a0[j0];
            a[0] = av.x; a[1] = av.y; a[2] = av.z; a[3] = av.w;
        }

        // ---- prologue: blocks 0 and 1 (A = a0, no commits) ----
        {
            float k0a[4], k1a[4], k2a[4], v0a[4], v1a[4], v2a[4], v3a[4];
            #pragma unroll
            for (int e = 0; e < 4; e++) {
                k0a[e] = ((const float*)&k8[0])[e];
                k1a[e] = ((const float*)&k8[1])[e];
                k2a[e] = ((const float*)&k8[2])[e];
                v0a[e] = ((const float*)&v8[0])[e];
                v1a[e] = ((const float*)&v8[1])[e];
                v2a[e] = ((const float*)&v8[2])[e];
                v3a[e] = ((const float*)&v8[3])[e];
            }
            // block 0: steps 0,1.  q all = V0.sig(a0); o_{cbd} depends only on d.
            float z = 0.f, oA = 0.f, oB = 0.f;
            // block 1: steps 2,3.  factors: c->K0, b->K1, d->K2
            float q0=0,q1=0,q2=0,q3=0, p0=0,p1=0,p2=0,p3=0,p4=0,p5=0,p6=0,p7=0;
            #pragma unroll
            for (int e = 0; e < 4; e++) {
                float E0 = __expf(-a[e]);
                float sa = __fdividef(1.f, 1.f + E0);            // sig(a0)
                float sb = __fdividef(1.f, 1.f + E0 * k0a[e]);   // sig(a0+W0)
                z  = fmaf(v0a[e], sa, z);
                oA = fmaf(v1a[e], sa, oA);
                oB = fmaf(v1a[e], sb, oB);
                // block-1 states
                float Ec  = E0 * k0a[e];
                float E00 = E0,          E10 = Ec;
                float E01 = E0 * k1a[e], E11 = Ec * k1a[e];
                float s000 = __fdividef(1.f, 1.f + E00);
                float s100 = __fdividef(1.f, 1.f + E10);
                float s010 = __fdividef(1.f, 1.f + E01);
                float s110 = __fdividef(1.f, 1.f + E11);
                float s001 = __fdividef(1.f, 1.f + E00 * k2a[e]);
                float s101 = __fdividef(1.f, 1.f + E10 * k2a[e]);
                float s011 = __fdividef(1.f, 1.f + E01 * k2a[e]);
                float s111 = __fdividef(1.f, 1.f + E11 * k2a[e]);
                q0 = fmaf(v2a[e], s000, q0);
                q1 = fmaf(v2a[e], s010, q1);
                q2 = fmaf(v2a[e], s100, q2);
                q3 = fmaf(v2a[e], s110, q3);
                p0 = fmaf(v3a[e], s000, p0);
                p1 = fmaf(v3a[e], s001, p1);
                p2 = fmaf(v3a[e], s010, p2);
                p3 = fmaf(v3a[e], s011, p3);
                p4 = fmaf(v3a[e], s100, p4);
                p5 = fmaf(v3a[e], s101, p5);
                p6 = fmaf(v3a[e], s110, p6);
                p7 = fmaf(v3a[e], s111, p7);
            }
            publish(0, z, z, z, z, oA, oB, oA, oB, oA, oB, oA, oB);
            publish(1, q0, q1, q2, q3, p0, p1, p2, p3, p4, p5, p6, p7);
        }

        // ---- main loop: blocks t = 2 .. NB-1 ----
        #pragma unroll 4
        for (int t = 2; t < NB; t++) {
            // copy ring locals FIRST (prefetch below overwrites W commit slots)
            float wca[4], wba[4], k2a[4], k1a[4], k0a[4], vea[4], voa[4];
            {
                float4 wc = w8[(2*t - 4) & 7], wb = w8[(2*t - 3) & 7];
                float4 kk2 = k8[(2*t - 2) & 7], kk1 = k8[(2*t - 1) & 7], kk0 = k8[(2*t) & 7];
                float4 ve = v8[(2*t) & 7], vo = v8[(2*t + 1) & 7];
                #pragma unroll
                for (int e = 0; e < 4; e++) {
                    wca[e] = ((const float*)&wc)[e];
                    wba[e] = ((const float*)&wb)[e];
                    k2a[e] = ((const float*)&kk2)[e];
                    k1a[e] = ((const float*)&kk1)[e];
                    k0a[e] = ((const float*)&kk0)[e];
                    vea[e] = ((const float*)&ve)[e];
                    voa[e] = ((const float*)&vo)[e];
                }
            }
            // prefetch rows 2t+4, 2t+5 (for block t+2)
            int ra = (2*t + 4 < S) ? 2*t + 4 : S - 1;
            int rb = (2*t + 5 < S) ? 2*t + 5 : S - 1;
            w8[(2*t + 4) & 7] = *(const float4*)&g_Wt[(size_t)ra * H + j0];
            k8[(2*t + 4) & 7] = *(const float4*)&g_Kt[(size_t)ra * H + j0];
            v8[(2*t + 4) & 7] = *(const float4*)&V[(size_t)ra * H + j0];
            w8[(2*t + 5) & 7] = *(const float4*)&g_Wt[(size_t)rb * H + j0];
            k8[(2*t + 5) & 7] = *(const float4*)&g_Kt[(size_t)rb * H + j0];
            v8[(2*t + 5) & 7] = *(const float4*)&V[(size_t)rb * H + j0];

            // wait block decision t-2: (s_{2t-4}, s_{2t-3})
            unsigned d;
            do { d = decv[(t - 2) & (RDEP - 1)]; } while ((d >> 2) != (unsigned)(t - 2));
            const float c0 = (float)(d & 1);
            const float b0 = (float)((d >> 1) & 1);

            float q0=0,q1=0,q2=0,q3=0, p0=0,p1=0,p2=0,p3=0,p4=0,p5=0,p6=0,p7=0;
            #pragma unroll
            for (int e = 0; e < 4; e++) {
                a[e] = fmaf(c0, wca[e], a[e]);
                a[e] = fmaf(b0, wba[e], a[e]);
                float E0 = __expf(-a[e]);
                float Ec  = E0 * k2a[e];
                float E00 = E0,          E10 = Ec;
                float E01 = E0 * k1a[e], E11 = Ec * k1a[e];
                float s000 = __fdividef(1.f, 1.f + E00);
                float s100 = __fdividef(1.f, 1.f + E10);
                float s010 = __fdividef(1.f, 1.f + E01);
                float s110 = __fdividef(1.f, 1.f + E11);
                float s001 = __fdividef(1.f, 1.f + E00 * k0a[e]);
                float s101 = __fdividef(1.f, 1.f + E10 * k0a[e]);
                float s011 = __fdividef(1.f, 1.f + E01 * k0a[e]);
                float s111 = __fdividef(1.f, 1.f + E11 * k0a[e]);
                q0 = fmaf(vea[e], s000, q0);
                q1 = fmaf(vea[e], s010, q1);
                q2 = fmaf(vea[e], s100, q2);
                q3 = fmaf(vea[e], s110, q3);
                p0 = fmaf(voa[e], s000, p0);
                p1 = fmaf(voa[e], s001, p1);
                p2 = fmaf(voa[e], s010, p2);
                p3 = fmaf(voa[e], s011, p3);
                p4 = fmaf(voa[e], s100, p4);
                p5 = fmaf(voa[e], s101, p5);
                p6 = fmaf(voa[e], s110, p6);
                p7 = fmaf(voa[e], s111, p7);
            }
            publish(t, q0, q1, q2, q3, p0, p1, p2, p3, p4, p5, p6, p7);
        }
    } else if (wid == 0) {
        // ========== sender warp: pre-sum 12 entries, gate on bdec(t-1), send 3 ==========
        for (int t = 0; t < NB; t++) {
            const unsigned want = (unsigned)t;
            const int r = t & (RDEP - 1);
            uint4 u[NWW][6];
            for (;;) {
                bool ok = true;
                #pragma unroll
                for (int w = 0; w < NWW; w++)
                    #pragma unroll
                    for (int k = 0; k < 6; k++) {
                        u[w][k] = lds128v(&wpq[r][w][k]);
                        ok &= (u[w][k].x == want) & (u[w][k].w == want);
                    }
                if (ok) break;
            }
            // fixed-order sums over 8 warps for all 12 entries
            float sum[12];
            #pragma unroll
            for (int k = 0; k < 6; k++) {
                float sy = ((__uint_as_float(u[0][k].y) + __uint_as_float(u[1][k].y)) +
                            (__uint_as_float(u[2][k].y) + __uint_as_float(u[3][k].y))) +
                           ((__uint_as_float(u[4][k].y) + __uint_as_float(u[5][k].y)) +
                            (__uint_as_float(u[6][k].y) + __uint_as_float(u[7][k].y)));
                float sz = ((__uint_as_float(u[0][k].z) + __uint_as_float(u[1][k].z)) +
                            (__uint_as_float(u[2][k].z) + __uint_as_float(u[3][k].z))) +
                           ((__uint_as_float(u[4][k].z) + __uint_as_float(u[5][k].z)) +
                            (__uint_as_float(u[6][k].z) + __uint_as_float(u[7][k].z)));
                sum[k * 2]     = sy;
                sum[k * 2 + 1] = sz;
            }
            // sum[0..3] = q[cb] (cb = c*2+b), sum[4..11] = o[cb*2+d]
            unsigned c = 0, bb = 0;
            if (t >= 1) {
                unsigned d;
                do { d = decv[(t - 1) & (RDEP - 1)]; } while ((d >> 2) != (unsigned)(t - 1));
                c  = d & 1;          // s_{2t-2}
                bb = (d >> 1) & 1;   // s_{2t-1}
            }
            unsigned cb = c * 2 + bb;
            float Ev  = sum[cb];
            float O0v = sum[4 + cb * 2];
            float O1v = sum[4 + cb * 2 + 1];
            if (lane < 24) {
                int dst = lane & 7, idx = lane >> 3;
                float val = (idx == 0) ? Ev : (idx == 1) ? O0v : O1v;
                unsigned long long pk =
                    ((unsigned long long)want << 32) | (unsigned long long)__float_as_uint(val);
                remote_store64(smem_u32(&slots[r][(idx << 3) | (int)rank]), (unsigned)dst, pk);
            }
        }
    } else if (wid == 1) {
        // ========== decider warp: resolve TWO steps per exchange ==========
        const float2* bp = (const float2*)b;
        float2 bcur = bp[0], bnxt = (NB > 1) ? bp[1] : bp[0];
        float2 tcur0 = g_thr2[0], tcur1 = g_thr2[1];
        float2 tnxt0 = g_thr2[2], tnxt1 = g_thr2[3];
        unsigned sprev_odd = 0;   // s_{2t-1} (unused; kept via dec)
        const bool xwriter = (rank == 0 && lane == 0);

        for (int t = 0; t < NB; t++) {
            const unsigned want = (unsigned)t;
            const int r = t & (RDEP - 1);

            // prefetch b/thr for block t+2
            int tp = (t + 2 < NB) ? t + 2 : NB - 1;
            float2 bf = bp[tp];
            float2 tf0 = g_thr2[2 * tp], tf1 = g_thr2[2 * tp + 1];

            // poll my slot word (lanes 0..23)
            volatile unsigned long long* sv = &slots[r][0];
            unsigned long long v = 0;
            if (lane < 24) v = sv[lane];
            while (!__all_sync(FULL, (lane >= 24) || ((unsigned)(v >> 32) == want))) {
                if (lane < 24) v = sv[lane];
            }
            float f = (lane < 24) ? __uint_as_float((unsigned)v) : 0.f;
            // sum over src within each idx group (lane = idx*8 + src)
            f += __shfl_xor_sync(FULL, f, 1);
            f += __shfl_xor_sync(FULL, f, 2);
            f += __shfl_xor_sync(FULL, f, 4);
            float E  = __shfl_sync(FULL, f, 0);
            float O0 = __shfl_sync(FULL, f, 8);
            float O1 = __shfl_sync(FULL, f, 16);

            // resolve step 2t
            float xe = bcur.x + E;
            bool  se = thr_cmp(xe, tcur0);
            // resolve step 2t+1
            float xo = bcur.y + (se ? O1 : O0);
            bool  so = thr_cmp(xo, tcur1);

            if (lane == 0) {
                decv[r] = (want << 2) | ((unsigned)so << 1) | (unsigned)se;
            }
            if (xwriter) {
                xwv[2 * t]     = ((unsigned long long)(unsigned)(2 * t) << 32) |
                                 (unsigned long long)__float_as_uint(xe);
                xwv[2 * t + 1] = ((unsigned long long)(unsigned)(2 * t + 1) << 32) |
                                 (unsigned long long)__float_as_uint(xo);
            }
            (void)sprev_odd;

            bcur = bnxt; bnxt = bf;
            tcur0 = tnxt0; tcur1 = tnxt1; tnxt0 = tf0; tnxt1 = tf1;
        }
    } else {
        // ================= logp/output warp (wid 2; rank 0, lane 0) =================
        if (rank == 0 && lane == 0) {
            float2 tc = g_thr2[0], tn = g_thr2[1];
            double lp = 0.0;
            for (int i = 0; i < S; i++) {
                unsigned long long xv;
                do { xv = xwv[i]; } while ((unsigned)(xv >> 32) != (unsigned)i);
                float x = __uint_as_float((unsigned)xv);
                bool  s = thr_cmp(x, tc);
                out[i] = s ? 1.0f : 0.0f;
                if (i < S - 2)
                    lp -= (double)(s ? softplusf(-x) : softplusf(x));
                int ip = (i + 2 < S) ? i + 2 : S - 1;
                float2 tf = g_thr2[ip];
                tc = tn; tn = tf;
            }
            out[S] = (float)lp;
            for (int k = S + 1; k < out_size; k++) out[k] = 0.f;
        }
    }

    cluster_barrier();   // no CTA exits while peers may still store to its smem
}

// ---------------- launch ----------------
extern "C" void kernel_launch(void* const* d_in, const int* in_sizes, int n_in,
                              void* d_out, int out_size) {
    const float* ctxv = nullptr;
    const float* u    = nullptr;
    const float* W    = nullptr;
    const float* V    = nullptr;
    const float* b    = nullptr;
    const float* c    = nullptr;

    const int szW = (CTX + S) * H;   // 67108864
    const int szV = S * H;           // 33554432
    int n4seen = 0;
    for (int idx = 0; idx < n_in; idx++) {
        int sz = in_sizes[idx];
        const float* p = (const float*)d_in[idx];
        if (sz == szW)       W = p;
        else if (sz == szV)  V = p;
        else if (sz == H)    c = p;
        else if (sz == S) {
            if      (n4seen == 0) ctxv = p;
            else if (n4seen == 1) u    = p;
            else                  b    = p;
            n4seen++;
        }
    }
    if (!ctxv) ctxv = (const float*)d_in[0];
    if (!u)    u    = (const float*)d_in[1];
    if (!W)    W    = (const float*)d_in[2];
    if (!V)    V    = (const float*)d_in[3];
    if (!b)    b    = (const float*)d_in[4];
    if (!c)    c    = (const float*)d_in[5];

    float* out = (float*)d_out;

    gemv_kernel<<<H, 256>>>(W, ctxv, c);
    transpose_kernel<<<dim3(S / 32, H / 32), dim3(32, 8)>>>(W);
    thr_kernel<<<(S + 255) / 256, 256>>>(u);
    nade_kernel<<<CSZ, TPB>>>(V, b, out, out_size);
}

// round 14
// speedup vs baseline: 1.9498x; 1.9498x over previous
#include <cuda_runtime.h>
#include <cstdint>
#include <math.h>

#define H    8192      // DIM_HIDDEN
#define S    4096      // DIM_SOL (steps)
#define CTX  4096      // DIM_CONTEXT
#define CSZ  8         // cluster size
#define NWW  8         // worker warps per CTA (wids 3..10)
#define WTH  256       // worker threads per CTA
#define TPB  352       // sender(0) + decider(1) + logp(2) + 8 workers
#define DDEP 4         // wpq + dec ring depth
#define SDEP 8         // slots ring depth (span-3 causal chain needs >= 6)

// ---------------- device scratch (static, no allocs) ----------------
__device__ float  g_Wt[(size_t)S * H];   // transposed W[:, CTX:]
__device__ float  g_Kt[(size_t)S * H];   // exp(-g_Wt)
__device__ float  g_a0[H];               // a0 = c + W[:, :CTX] @ context
__device__ float2 g_thr2[S];             // (t_hi, t_lo) two-float logit(u_i)

// ---------------- helpers ----------------
__device__ __forceinline__ float sigmoidf_fast(float x) {
    return __fdividef(1.0f, 1.0f + __expf(-x));
}
__device__ __forceinline__ float softplusf(float y) {
    float t = fabsf(y);
    float r = log1pf(__expf(-t));
    return (y > 0.f) ? (y + r) : r;
}
__device__ __forceinline__ unsigned cluster_rank() {
    unsigned r; asm("mov.u32 %0, %%cluster_ctarank;" : "=r"(r)); return r;
}
__device__ __forceinline__ uint32_t smem_u32(const void* p) {
    return (uint32_t)__cvta_generic_to_shared(p);
}
__device__ __forceinline__ void remote_store64(uint32_t laddr, unsigned rank, unsigned long long v) {
    uint32_t raddr;
    asm volatile("mapa.shared::cluster.u32 %0, %1, %2;" : "=r"(raddr) : "r"(laddr), "r"(rank));
    asm volatile("st.relaxed.cluster.shared::cluster.b64 [%0], %1;" :: "r"(raddr), "l"(v) : "memory");
}
__device__ __forceinline__ void cluster_barrier() {
    asm volatile("barrier.cluster.arrive.aligned;" ::: "memory");
    asm volatile("barrier.cluster.wait.aligned;"   ::: "memory");
}
__device__ __forceinline__ uint4 lds128v(const void* p) {
    uint4 r;
    asm volatile("ld.volatile.shared.v4.b32 {%0,%1,%2,%3}, [%4];"
                 : "=r"(r.x), "=r"(r.y), "=r"(r.z), "=r"(r.w) : "r"(smem_u32(p)));
    return r;
}
__device__ __forceinline__ void sts128(void* p, unsigned a, unsigned b, unsigned c, unsigned d) {
    asm volatile("st.shared.v4.b32 [%0], {%1,%2,%3,%4};"
                 :: "r"(smem_u32(p)), "r"(a), "r"(b), "r"(c), "r"(d) : "memory");
}
// interleaved quad warp-sum (workers only; 3T of slack)
__device__ __forceinline__ void bfly4(float& a, float& b, float& c, float& d) {
    #pragma unroll
    for (int o = 16; o > 0; o >>= 1) {
        a += __shfl_xor_sync(0xffffffffu, a, o);
        b += __shfl_xor_sync(0xffffffffu, b, o);
        c += __shfl_xor_sync(0xffffffffu, c, o);
        d += __shfl_xor_sync(0xffffffffu, d, o);
    }
}
__device__ __forceinline__ bool thr_cmp(float x, float2 t) {
    return (x > t.x) || ((x == t.x) && (t.y < 0.f));
}

// ---------------- init kernels ----------------
__global__ void gemv_kernel(const float* __restrict__ W,
                            const float* __restrict__ ctxv,
                            const float* __restrict__ c) {
    __shared__ float sred[256];
    int r = blockIdx.x;
    const float* row = W + (size_t)r * (CTX + S);
    float acc = 0.f;
    for (int k = threadIdx.x; k < CTX; k += 256)
        acc += row[k] * ctxv[k];
    sred[threadIdx.x] = acc;
    __syncthreads();
    for (int off = 128; off > 0; off >>= 1) {
        if (threadIdx.x < off) sred[threadIdx.x] += sred[threadIdx.x + off];
        __syncthreads();
    }
    if (threadIdx.x == 0) g_a0[r] = c[r] + sred[0];
}

// transpose W[:, CTX:] and emit both Wt and Kt = exp(-Wt) in one pass
__global__ void transpose_kernel(const float* __restrict__ W) {
    __shared__ float tile[32][33];
    int i0 = blockIdx.x * 32;
    int j0 = blockIdx.y * 32;
    int tx = threadIdx.x;
    #pragma unroll
    for (int t = 0; t < 4; t++) {
        int ty = threadIdx.y + t * 8;
        tile[ty][tx] = W[(size_t)(j0 + ty) * (CTX + S) + CTX + i0 + tx];
    }
    __syncthreads();
    #pragma unroll
    for (int t = 0; t < 4; t++) {
        int ty = threadIdx.y + t * 8;
        float w = tile[tx][ty];
        size_t idx = (size_t)(i0 + ty) * H + j0 + tx;
        g_Wt[idx] = w;
        g_Kt[idx] = __expf(-w);
    }
}

__global__ void thr_kernel(const float* __restrict__ u) {
    int i = blockIdx.x * 256 + threadIdx.x;
    if (i < S) {
        double ud = (double)u[i];
        double t  = log(ud / (1.0 - ud));
        float hi  = (float)t;
        float lo  = (float)(t - (double)hi);
        g_thr2[i] = make_float2(hi, lo);
    }
}

// ---------------- main sequential kernel: 8-CTA cluster ----------------
// wpq[r][w][c] = {tag, z_c0, z_c1, tag} per worker warp w (c = s_{p-2} branch)
// slots[r][q*8 + src] = tagged 64-bit {tag|F_q}, q = c*2+b (UNselected quad)
// dec[r] = (step<<1) | s
__global__ void __cluster_dims__(CSZ, 1, 1) __launch_bounds__(TPB, 1)
nade_kernel(const float* __restrict__ V,
            const float* __restrict__ b,
            float* __restrict__ out,
            int out_size) {
    __shared__ __align__(16) uint4              wpq[DDEP][NWW][2];
    __shared__ __align__(16) unsigned long long slots[SDEP][32];
    __shared__ unsigned int       dec[DDEP];
    __shared__ unsigned long long xw[S];

    const unsigned rank = cluster_rank();
    const int tid  = threadIdx.x;
    const int wid  = tid >> 5;
    const int lane = tid & 31;
    const unsigned FULL = 0xffffffffu;

    for (int k = tid; k < DDEP * NWW * 2; k += TPB)
        ((uint4*)wpq)[k] = make_uint4(0xFFFFFFFFu, 0, 0, 0xFFFFFFFFu);
    for (int k = tid; k < SDEP * 32; k += TPB)
        ((unsigned long long*)slots)[k] = 0xFFFFFFFF00000000ULL;
    if (tid < DDEP) dec[tid] = 0xFFFFFFFFu;
    for (int k = tid; k < S; k += TPB)
        xw[k] = 0xFFFFFFFF00000000ULL;
    __syncthreads();
    cluster_barrier();   // all slots initialized before any remote store

    volatile unsigned int*       decv = dec;
    volatile unsigned long long* xwv  = xw;

    if (wid >= 3) {
        // ================= worker warps (wids 3..10), lag-3, 4-way speculation =====
        const int w    = wid - 3;
        const int wtid = tid - 96;                       // 0..255
        const int j0   = (int)rank * (WTH * 4) + wtid * 4;

        float a[4];
        float s00[4], s01[4], s10[4], s11[4];            // sig quad (current step)
        float4 w8[8], k8[8], v8[8];                      // register rings

        auto publish = [&](int p, float z00, float z01, float z10, float z11) {
            bfly4(z00, z01, z10, z11);
            if (lane == 0) {
                unsigned tg = (unsigned)p;
                const int r = p & (DDEP - 1);
                sts128(&wpq[r][w][0], tg, __float_as_uint(z00), __float_as_uint(z01), tg);
                sts128(&wpq[r][w][1], tg, __float_as_uint(z10), __float_as_uint(z11), tg);
            }
        };

        // ---- prologue: quads 0,1,2; state for iter 3 ----
        {
            float4 av = *(const float4*)&g_a0[j0];
            float4 w0 = *(const float4*)&g_Wt[j0];
            float4 w1 = *(const float4*)&g_Wt[(size_t)1 * H + j0];
            float4 v0 = *(const float4*)&V[j0];
            float4 v1 = *(const float4*)&V[(size_t)1 * H + j0];
            float4 v2 = *(const float4*)&V[(size_t)2 * H + j0];
            const float ava[4] = {av.x, av.y, av.z, av.w};
            const float w0a[4] = {w0.x, w0.y, w0.z, w0.w};
            const float w1a[4] = {w1.x, w1.y, w1.z, w1.w};
            const float v0a[4] = {v0.x, v0.y, v0.z, v0.w};
            const float v1a[4] = {v1.x, v1.y, v1.z, v1.w};
            const float v2a[4] = {v2.x, v2.y, v2.z, v2.w};

            float z = 0.f, zA = 0.f, zB = 0.f;
            float q00 = 0.f, q01 = 0.f, q10 = 0.f, q11 = 0.f;
            #pragma unroll
            for (int e = 0; e < 4; e++) {
                a[e] = ava[e];
                float h0 = sigmoidf_fast(a[e]);
                s00[e] = h0;
                s10[e] = sigmoidf_fast(a[e] + w0a[e]);
                s01[e] = sigmoidf_fast(a[e] + w1a[e]);
                s11[e] = sigmoidf_fast(a[e] + w0a[e] + w1a[e]);
                z  = fmaf(v0a[e], h0, z);
                zA = fmaf(v1a[e], h0, zA);
                zB = fmaf(v1a[e], s10[e], zB);
                q00 = fmaf(v2a[e], s00[e], q00);
                q01 = fmaf(v2a[e], s01[e], q01);
                q10 = fmaf(v2a[e], s10[e], q10);
                q11 = fmaf(v2a[e], s11[e], q11);
            }
            publish(0, z,  z,  z,  z);
            publish(1, zA, zB, zA, zB);
            publish(2, q00, q01, q10, q11);

            #pragma unroll
            for (int rI = 0; rI < 7; rI++) {
                w8[rI] = *(const float4*)&g_Wt[(size_t)rI * H + j0];
                k8[rI] = *(const float4*)&g_Kt[(size_t)rI * H + j0];
                v8[rI] = *(const float4*)&V[(size_t)rI * H + j0];
            }
        }

        // ---- main loop ----
        #pragma unroll 8
        for (int p = 3; p < 3 + 4096; p++) {
            int pf = (p + 4 < S) ? p + 4 : S - 1;
            w8[(p + 4) & 7] = *(const float4*)&g_Wt[(size_t)pf * H + j0];
            k8[(p + 4) & 7] = *(const float4*)&g_Kt[(size_t)pf * H + j0];
            v8[(p + 4) & 7] = *(const float4*)&V[(size_t)pf * H + j0];

            // pre-dec: xpre = exp(-(A_{p-4} + W_{p-1}))
            float4 wm1 = w8[(p - 1) & 7];
            float xpre[4];
            xpre[0] = __expf(-(a[0] + wm1.x));
            xpre[1] = __expf(-(a[1] + wm1.y));
            xpre[2] = __expf(-(a[2] + wm1.z));
            xpre[3] = __expf(-(a[3] + wm1.w));

            unsigned d;
            do { d = decv[(p - 3) & (DDEP - 1)]; } while ((d >> 1) != (unsigned)(p - 3));
            const bool  s  = (d & 1);
            const float sm = (float)(d & 1);

            float4 wm3 = w8[(p - 3) & 7];
            float4 km3 = k8[(p - 3) & 7];
            float4 km2 = k8[(p - 2) & 7];
            float4 vp  = v8[p & 7];
            const float wm3a[4] = {wm3.x, wm3.y, wm3.z, wm3.w};
            const float km3a[4] = {km3.x, km3.y, km3.z, km3.w};
            const float km2a[4] = {km2.x, km2.y, km2.z, km2.w};
            const float vpa[4]  = {vp.x,  vp.y,  vp.z,  vp.w};

            float z00 = 0.f, z01 = 0.f, z10 = 0.f, z11 = 0.f;
            #pragma unroll
            for (int e = 0; e < 4; e++) {
                a[e] = fmaf(sm, wm3a[e], a[e]);
                float Xi  = s ? xpre[e] * km3a[e] : xpre[e];
                float n00 = s ? s10[e] : s00[e];
                float n10 = s ? s11[e] : s01[e];
                float n01 = __fdividef(1.f, 1.f + Xi);
                float n11 = __fdividef(1.f, 1.f + Xi * km2a[e]);
                z00 = fmaf(vpa[e], n00, z00);
                z01 = fmaf(vpa[e], n01, z01);
                z10 = fmaf(vpa[e], n10, z10);
                z11 = fmaf(vpa[e], n11, z11);
                s00[e] = n00; s01[e] = n01; s10[e] = n10; s11[e] = n11;
            }
            if (p < S) publish(p, z00, z01, z10, z11);
        }
    } else if (wid == 0) {
        // ====== sender warp: NO decision gate — ship the full unselected quad ======
        for (int p = 0; p < S; p++) {
            const unsigned want = (unsigned)p;
            const int rw = p & (DDEP - 1);
            const int rs = p & (SDEP - 1);
            uint4 u0[NWW], u1[NWW];
            for (;;) {
                bool ok = true;
                #pragma unroll
                for (int w = 0; w < NWW; w++) {
                    u0[w] = lds128v(&wpq[rw][w][0]);
                    u1[w] = lds128v(&wpq[rw][w][1]);
                    ok &= (u0[w].x == want) & (u0[w].w == want)
                        & (u1[w].x == want) & (u1[w].w == want);
                }
                if (ok) break;
            }
            // fixed-order trees over 8 warps for all 4 quad entries
            float F0 = ((__uint_as_float(u0[0].y) + __uint_as_float(u0[1].y)) +
                        (__uint_as_float(u0[2].y) + __uint_as_float(u0[3].y))) +
                       ((__uint_as_float(u0[4].y) + __uint_as_float(u0[5].y)) +
                        (__uint_as_float(u0[6].y) + __uint_as_float(u0[7].y)));
            float F1 = ((__uint_as_float(u0[0].z) + __uint_as_float(u0[1].z)) +
                        (__uint_as_float(u0[2].z) + __uint_as_float(u0[3].z))) +
                       ((__uint_as_float(u0[4].z) + __uint_as_float(u0[5].z)) +
                        (__uint_as_float(u0[6].z) + __uint_as_float(u0[7].z)));
            float F2 = ((__uint_as_float(u1[0].y) + __uint_as_float(u1[1].y)) +
                        (__uint_as_float(u1[2].y) + __uint_as_float(u1[3].y))) +
                       ((__uint_as_float(u1[4].y) + __uint_as_float(u1[5].y)) +
                        (__uint_as_float(u1[6].y) + __uint_as_float(u1[7].y)));
            float F3 = ((__uint_as_float(u1[0].z) + __uint_as_float(u1[1].z)) +
                        (__uint_as_float(u1[2].z) + __uint_as_float(u1[3].z))) +
                       ((__uint_as_float(u1[4].z) + __uint_as_float(u1[5].z)) +
                        (__uint_as_float(u1[6].z) + __uint_as_float(u1[7].z)));
            // lane = q*8 + dst : one remote store per lane (32 total)
            float val = (lane < 8) ? F0 : (lane < 16) ? F1 : (lane < 24) ? F2 : F3;
            unsigned long long pk =
                ((unsigned long long)want << 32) | (unsigned long long)__float_as_uint(val);
            remote_store64(smem_u32(&slots[rs][(lane & 24) | (int)rank]),
                           (unsigned)(lane & 7), pk);
        }
    } else if (wid == 1) {
        // ====== decider warp: poll 32 words, reduce, DOUBLE-select locally ======
        float  bc = b[0],      bn = b[1];
        float2 tc = g_thr2[0], tn = g_thr2[1];
        unsigned sp1 = 0, sp2 = 0;     // s_{i-1}, s_{i-2}
        const bool xwriter = (rank == 0 && lane == 0);

        for (int i = 0; i < S; i++) {
            const unsigned want = (unsigned)i;
            const int rs = i & (SDEP - 1);

            volatile unsigned long long* sv = &slots[rs][0];
            unsigned long long v = sv[lane];
            while (!__all_sync(FULL, (unsigned)(v >> 32) == want))
                v = sv[lane];

            // lane = q*8 + src: sum over src (xor 1,2,4 stays within q group)
            float f = __uint_as_float((unsigned)v);
            f += __shfl_xor_sync(FULL, f, 1);
            f += __shfl_xor_sync(FULL, f, 2);
            f += __shfl_xor_sync(FULL, f, 4);

            // select quad entry q = (s_{i-2}<<1) | s_{i-1}
            unsigned sel = (sp2 << 1) | sp1;
            float D = __shfl_sync(FULL, f, (int)(sel << 3));

            float x = bc + D;
            bool  s = thr_cmp(x, tc);
            sp2 = sp1; sp1 = (unsigned)s;

            if (lane == 0)
                decv[i & (DDEP - 1)] = (want << 1) | (unsigned)s;
            if (xwriter)
                xwv[i] = ((unsigned long long)want << 32) |
                         (unsigned long long)__float_as_uint(x);

            int ip = (i + 2 < S) ? i + 2 : S - 1;
            float bf = b[ip]; float2 tf = g_thr2[ip];
            bc = bn; bn = bf; tc = tn; tn = tf;
        }
    } else {
        // ================= logp/output warp (wid 2; rank 0, lane 0) =================
        if (rank == 0 && lane == 0) {
            float2 tc = g_thr2[0], tn = g_thr2[1];
            double lp = 0.0;
            for (int i = 0; i < S; i++) {
                unsigned long long xv;
                do { xv = xwv[i]; } while ((unsigned)(xv >> 32) != (unsigned)i);
                float x = __uint_as_float((unsigned)xv);
                bool  s = thr_cmp(x, tc);
                out[i] = s ? 1.0f : 0.0f;
                if (i < S - 2)
                    lp -= (double)(s ? softplusf(-x) : softplusf(x));
                int ip = (i + 2 < S) ? i + 2 : S - 1;
                float2 tf = g_thr2[ip];
                tc = tn; tn = tf;
            }
            out[S] = (float)lp;
            for (int k = S + 1; k < out_size; k++) out[k] = 0.f;
        }
    }

    cluster_barrier();   // no CTA exits while peers may still store to its smem
}

// ---------------- launch ----------------
extern "C" void kernel_launch(void* const* d_in, const int* in_sizes, int n_in,
                              void* d_out, int out_size) {
    const float* ctxv = nullptr;
    const float* u    = nullptr;
    const float* W    = nullptr;
    const float* V    = nullptr;
    const float* b    = nullptr;
    const float* c    = nullptr;

    const int szW = (CTX + S) * H;   // 67108864
    const int szV = S * H;           // 33554432
    int n4seen = 0;
    for (int idx = 0; idx < n_in; idx++) {
        int sz = in_sizes[idx];
        const float* p = (const float*)d_in[idx];
        if (sz == szW)       W = p;
        else if (sz == szV)  V = p;
        else if (sz == H)    c = p;
        else if (sz == S) {
            if      (n4seen == 0) ctxv = p;
            else if (n4seen == 1) u    = p;
            else                  b    = p;
            n4seen++;
        }
    }
    if (!ctxv) ctxv = (const float*)d_in[0];
    if (!u)    u    = (const float*)d_in[1];
    if (!W)    W    = (const float*)d_in[2];
    if (!V)    V    = (const float*)d_in[3];
    if (!b)    b    = (const float*)d_in[4];
    if (!c)    c    = (const float*)d_in[5];

    float* out = (float*)d_out;

    gemv_kernel<<<H, 256>>>(W, ctxv, c);
    transpose_kernel<<<dim3(S / 32, H / 32), dim3(32, 8)>>>(W);
    thr_kernel<<<(S + 255) / 256, 256>>>(u);
    nade_kernel<<<CSZ, TPB>>>(V, b, out, out_size);
}